// round 6
// baseline (speedup 1.0000x reference)
#include <cuda_runtime.h>
#include <cuda_fp16.h>
#include <math.h>
#include <stdint.h>

#define BATCH 8
#define SEQ   2048
#define HID   1024
#define BS    (BATCH*SEQ)

typedef __half fp16;

// ---------------------------------------------------------------------------
// Scratch (device globals — allocation is forbidden)
// ---------------------------------------------------------------------------
__device__ fp16 g_Xh[(size_t)BS * HID];
__device__ fp16 g_Wqt_hi[(size_t)HID * HID], g_Wqt_lo[(size_t)HID * HID];
__device__ fp16 g_Wkt_hi[(size_t)HID * HID], g_Wkt_lo[(size_t)HID * HID];
__device__ fp16 g_Wvt_hi[(size_t)HID * HID], g_Wvt_lo[(size_t)HID * HID];
__device__ fp16 g_Qh[(size_t)BS * HID];
__device__ fp16 g_Khi[(size_t)BS * HID], g_Klo[(size_t)BS * HID];
__device__ fp16 g_Vh[(size_t)BS * HID];
__device__ fp16 g_Vt[(size_t)BS * HID];
__device__ float g_S[(size_t)BATCH * SEQ * SEQ];
__device__ fp16 g_P[(size_t)BATCH * SEQ * SEQ];

// ---------------------------------------------------------------------------
// Helpers
// ---------------------------------------------------------------------------
__device__ __forceinline__ uint32_t smem_u32(const void* p) {
    uint32_t a;
    asm("{ .reg .u64 t; cvta.to.shared.u64 t, %1; cvt.u32.u64 %0, t; }" : "=r"(a) : "l"(p));
    return a;
}

__device__ __forceinline__ void cp_async16(uint32_t dst, const void* src) {
    asm volatile("cp.async.cg.shared.global [%0], [%1], 16;" :: "r"(dst), "l"(src));
}
__device__ __forceinline__ void cp_commit() {
    asm volatile("cp.async.commit_group;");
}
template<int N>
__device__ __forceinline__ void cp_wait() {
    asm volatile("cp.async.wait_group %0;" :: "n"(N));
}

__device__ __forceinline__ void ldsm4(uint32_t* r, uint32_t addr) {
    asm volatile("ldmatrix.sync.aligned.m8n8.x4.shared.b16 {%0,%1,%2,%3}, [%4];"
                 : "=r"(r[0]), "=r"(r[1]), "=r"(r[2]), "=r"(r[3]) : "r"(addr));
}

__device__ __forceinline__ void mma16816(float* d, const uint32_t* a, const uint32_t* b) {
    asm volatile(
        "mma.sync.aligned.m16n8k16.row.col.f32.f16.f16.f32 "
        "{%0,%1,%2,%3}, {%4,%5,%6,%7}, {%8,%9}, {%0,%1,%2,%3};"
        : "+f"(d[0]), "+f"(d[1]), "+f"(d[2]), "+f"(d[3])
        : "r"(a[0]), "r"(a[1]), "r"(a[2]), "r"(a[3]), "r"(b[0]), "r"(b[1]));
}

// SW128 swizzle of a byte offset within a tile of 128-byte rows
__device__ __forceinline__ uint32_t sw128(uint32_t off) {
    return off ^ ((off >> 3) & 0x70);
}

// ---------------------------------------------------------------------------
// Elementwise round: fp32 -> fp16
// ---------------------------------------------------------------------------
__global__ __launch_bounds__(256) void round_kernel(
    const float* __restrict__ x, fp16* __restrict__ h, long n)
{
    long i = ((long)blockIdx.x * 256 + threadIdx.x) * 4;
    if (i >= n) return;
    float4 v = *(const float4*)(x + i);
    *(half2*)(h + i)     = __floats2half2_rn(v.x, v.y);
    *(half2*)(h + i + 2) = __floats2half2_rn(v.z, v.w);
}

// W [K=H, N=H] fp32 -> Wt [N, K] (hi, lo) fp16, scaled by 32 (exact pow2).
// Scaling keeps lo-terms in fp16 normal range; epilogue multiplies by 1/32.
__global__ __launch_bounds__(256) void wtrans_kernel(
    const float* __restrict__ W, fp16* __restrict__ hi, fp16* __restrict__ lo)
{
    __shared__ float t[32][33];
    int tx = threadIdx.x, ty = threadIdx.y;
    int x0 = blockIdx.x * 32, y0 = blockIdx.y * 32;
    #pragma unroll
    for (int r = 0; r < 32; r += 8)
        t[ty + r][tx] = W[(long)(y0 + ty + r) * HID + x0 + tx];
    __syncthreads();
    #pragma unroll
    for (int r = 0; r < 32; r += 8) {
        float v = t[tx][ty + r] * 32.0f;
        long o = (long)(x0 + ty + r) * HID + y0 + tx;
        fp16 h = __float2half_rn(v);
        hi[o] = h;
        lo[o] = __float2half_rn(v - __half2float(h));
    }
}

// fp16 batched transpose: in [R, C] -> out [C, R] per batch (blockIdx.z)
__global__ __launch_bounds__(256) void btrans_kernel(
    const fp16* __restrict__ in, fp16* __restrict__ out, int R, int C)
{
    __shared__ fp16 t[32][33];
    int tx = threadIdx.x, ty = threadIdx.y;
    int x0 = blockIdx.x * 32, y0 = blockIdx.y * 32;
    in  += (long)blockIdx.z * R * C;
    out += (long)blockIdx.z * R * C;
    #pragma unroll
    for (int r = 0; r < 32; r += 8)
        t[ty + r][tx] = in[(long)(y0 + ty + r) * C + x0 + tx];
    __syncthreads();
    #pragma unroll
    for (int r = 0; r < 32; r += 8)
        out[(long)(x0 + ty + r) * R + y0 + tx] = t[tx][ty + r];
}

// ---------------------------------------------------------------------------
// HMMA fp16 GEMM (A single precision-level, B optionally hi/lo split):
//   PRODUCTS==2: C = Ah*(Bhi+Blo)^T   (2 mma products)
//   PRODUCTS==1: C = Ah*Bhi^T
// A: [M,K] K-major.  B: [N,K] K-major.  CTA tile 256x128, BK=64,
// 256 threads (8 warps, 4Mx2N, warp tile 64x64), 3-stage cp.async pipeline.
// OUTMODE: 0 = fp32, 1 = fp16 hi/lo, 2 = fp16 single.
// Epilogue: v = acc*cscale (+ bias).
// ---------------------------------------------------------------------------
#define TILE_B   16384                 // 128 rows x 128 bytes (64 fp16)
#define ATILE_B  32768                 // 256 rows x 128 bytes
#define STAGES   3

// Load one ROWSx64 fp16 tile (global, row stride ldk elems) into swizzled SMEM.
template<int ROWS>
__device__ __forceinline__ void load_tile_async(
    uint32_t dst, const fp16* __restrict__ src, int ldk, int tid)
{
    #pragma unroll
    for (int i = 0; i < ROWS / 32; i++) {
        int s = tid + i * 256;
        int row = s >> 3, seg = s & 7;
        uint32_t off = row * 128 + seg * 16;
        cp_async16(dst + sw128(off), src + (long)row * ldk + seg * 8);
    }
}

template<int OUTMODE, int PRODUCTS, bool ADD_BIAS>
__global__ __launch_bounds__(256, 1) void gemm_split_kernel(
    const fp16* __restrict__ Ah,
    const fp16* __restrict__ Bhi, const fp16* __restrict__ Blo,
    const float* __restrict__ bias, float cscale,
    float* __restrict__ Cf, fp16* __restrict__ Chi, fp16* __restrict__ Clo,
    int K, int Ncols, long sA, long sB, long sC)
{
    constexpr uint32_t STAGE_B = ATILE_B + ((PRODUCTS == 2) ? 2 : 1) * TILE_B;
    constexpr uint32_t OFF_A   = 0;
    constexpr uint32_t OFF_BHI = ATILE_B;
    constexpr uint32_t OFF_BLO = ATILE_B + TILE_B;           // P2 only

    extern __shared__ char smem[];
    const uint32_t tiles = (smem_u32(smem) + 1023) & ~1023u;

    const int tid = threadIdx.x;
    const int lane = tid & 31;
    const int w = tid >> 5;
    const int wm = w & 3;          // 0..3 : 64-row band
    const int wn = w >> 2;         // 0..1 : 64-col band
    const int bn = blockIdx.x, bm = blockIdx.y, bz = blockIdx.z;

    Ah  += bz * sA + (long)(bm * 256) * K;
    Bhi += bz * sB + (long)(bn * 128) * K;
    if (PRODUCTS == 2) Blo += bz * sB + (long)(bn * 128) * K;

    float acc[4][8][4];
    #pragma unroll
    for (int mt = 0; mt < 4; mt++)
        #pragma unroll
        for (int nt = 0; nt < 8; nt++)
            #pragma unroll
            for (int r = 0; r < 4; r++) acc[mt][nt][r] = 0.f;

    const int nchunks = K / 64;

    auto issue_chunk = [&](int cc) {
        const uint32_t buf = tiles + (uint32_t)(cc % STAGES) * STAGE_B;
        const long k0 = (long)cc * 64;
        load_tile_async<256>(buf + OFF_A, Ah + k0, K, tid);
        load_tile_async<128>(buf + OFF_BHI, Bhi + k0, K, tid);
        if (PRODUCTS == 2) load_tile_async<128>(buf + OFF_BLO, Blo + k0, K, tid);
        cp_commit();
    };

    // prologue: stages 0,1
    issue_chunk(0);
    issue_chunk(1);

    // ldmatrix base offsets (within a tile)
    const int arow = wm * 64 + (lane & 15);            // +mt*16
    const int brow = wn * 64 + (lane & 15);            // +nt2*16
    const uint32_t kseg = (lane >> 4) * 16;            // 16B half-select

    for (int c = 0; c < nchunks; c++) {
        if (c + 2 < nchunks) { issue_chunk(c + 2); cp_wait<2>(); }
        else if (c + 1 < nchunks) { cp_wait<1>(); }
        else { cp_wait<0>(); }
        __syncthreads();

        const uint32_t buf = tiles + (uint32_t)(c % STAGES) * STAGE_B;
        const uint32_t As   = buf + OFF_A;
        const uint32_t Bs_h = buf + OFF_BHI;
        const uint32_t Bs_l = buf + OFF_BLO;

        #pragma unroll
        for (int ks = 0; ks < 4; ks++) {
            const uint32_t kb = ks * 32 + kseg;   // byte col within 128B row
            uint32_t ah[4][4];
            #pragma unroll
            for (int mt = 0; mt < 4; mt++) {
                uint32_t off = (uint32_t)(arow + mt * 16) * 128 + kb;
                ldsm4(ah[mt], As + sw128(off));
            }
            #pragma unroll
            for (int nt2 = 0; nt2 < 4; nt2++) {
                uint32_t off = (uint32_t)(brow + nt2 * 16) * 128 + kb;
                uint32_t sw = sw128(off);
                uint32_t rh[4];
                ldsm4(rh, Bs_h + sw);
                uint32_t b0h[2] = {rh[0], rh[2]}, b1h[2] = {rh[1], rh[3]};
                #pragma unroll
                for (int mt = 0; mt < 4; mt++) {
                    mma16816(acc[mt][nt2 * 2 + 0], ah[mt], b0h);
                    mma16816(acc[mt][nt2 * 2 + 1], ah[mt], b1h);
                }
                if (PRODUCTS == 2) {
                    uint32_t rl[4];
                    ldsm4(rl, Bs_l + sw);
                    uint32_t b0l[2] = {rl[0], rl[2]}, b1l[2] = {rl[1], rl[3]};
                    #pragma unroll
                    for (int mt = 0; mt < 4; mt++) {
                        mma16816(acc[mt][nt2 * 2 + 0], ah[mt], b0l);
                        mma16816(acc[mt][nt2 * 2 + 1], ah[mt], b1l);
                    }
                }
            }
        }
        __syncthreads();
    }

    // ---- epilogue ----
    const int qr = lane >> 2;      // 0..7
    const int qc = lane & 3;       // 0..3
    #pragma unroll
    for (int mt = 0; mt < 4; mt++) {
        #pragma unroll
        for (int half_ = 0; half_ < 2; half_++) {   // d0,d1 vs d2,d3 (row, row+8)
            const long row = (long)(bm * 256 + wm * 64 + mt * 16 + qr + half_ * 8);
            const long cb = bz * sC + row * Ncols;
            #pragma unroll
            for (int nt = 0; nt < 8; nt++) {
                const int col = bn * 128 + wn * 64 + nt * 8 + qc * 2;
                float v0 = acc[mt][nt][half_ * 2 + 0] * cscale;
                float v1 = acc[mt][nt][half_ * 2 + 1] * cscale;
                if constexpr (ADD_BIAS) { v0 += bias[col]; v1 += bias[col + 1]; }
                if constexpr (OUTMODE == 0) {
                    *(float2*)(Cf + cb + col) = make_float2(v0, v1);
                } else if constexpr (OUTMODE == 1) {
                    fp16 h0 = __float2half_rn(v0);
                    fp16 h1 = __float2half_rn(v1);
                    fp16 l0 = __float2half_rn(v0 - __half2float(h0));
                    fp16 l1 = __float2half_rn(v1 - __half2float(h1));
                    *(half2*)(Chi + cb + col) = __halves2half2(h0, h1);
                    *(half2*)(Clo + cb + col) = __halves2half2(l0, l1);
                } else {
                    *(half2*)(Chi + cb + col) = __floats2half2_rn(v0, v1);
                }
            }
        }
    }
}

// ---------------------------------------------------------------------------
// Softmax over rows of scores [B,S,S] (already scaled by 1/32 in QK epilogue).
// Single global read (row cached in smem); emits probs as single fp16.
// ---------------------------------------------------------------------------
__global__ __launch_bounds__(256) void softmax_kernel(
    const float* __restrict__ S, const int* __restrict__ mask, fp16* __restrict__ P)
{
    const int row = blockIdx.x;
    const int b   = blockIdx.y;
    const long off = ((long)b * SEQ + row) * SEQ;
    const float* ptr = S + off;
    const int* mrow = mask + (long)b * SEQ;
    const int tid = threadIdx.x;

    __shared__ float buf[SEQ];
    __shared__ float red[256];

    float m = -INFINITY;
    #pragma unroll
    for (int k = tid * 4; k < SEQ; k += 1024) {
        float4 s = *(const float4*)(ptr + k);
        int4 mk = *(const int4*)(mrow + k);
        s.x = (mk.x == 0) ? -INFINITY : s.x;
        s.y = (mk.y == 0) ? -INFINITY : s.y;
        s.z = (mk.z == 0) ? -INFINITY : s.z;
        s.w = (mk.w == 0) ? -INFINITY : s.w;
        *(float4*)(buf + k) = s;
        m = fmaxf(m, fmaxf(fmaxf(s.x, s.y), fmaxf(s.z, s.w)));
    }
    red[tid] = m; __syncthreads();
    for (int o = 128; o > 0; o >>= 1) {
        if (tid < o) red[tid] = fmaxf(red[tid], red[tid + o]);
        __syncthreads();
    }
    m = red[0];
    __syncthreads();

    float sum = 0.f;
    #pragma unroll
    for (int k = tid * 4; k < SEQ; k += 1024) {
        float4 s = *(float4*)(buf + k);
        s.x = __expf(s.x - m); s.y = __expf(s.y - m);
        s.z = __expf(s.z - m); s.w = __expf(s.w - m);
        *(float4*)(buf + k) = s;
        sum += s.x + s.y + s.z + s.w;
    }
    red[tid] = sum; __syncthreads();
    for (int o = 128; o > 0; o >>= 1) {
        if (tid < o) red[tid] += red[tid + o];
        __syncthreads();
    }
    const float inv = 1.f / red[0];

    #pragma unroll
    for (int k = tid * 4; k < SEQ; k += 1024) {
        float4 e = *(float4*)(buf + k);
        *(half2*)(P + off + k)     = __floats2half2_rn(e.x * inv, e.y * inv);
        *(half2*)(P + off + k + 2) = __floats2half2_rn(e.z * inv, e.w * inv);
    }
}

// ---------------------------------------------------------------------------
extern "C" void kernel_launch(void* const* d_in, const int* in_sizes, int n_in,
                              void* d_out, int out_size)
{
    const float* inp  = (const float*)d_in[0];
    const int*   mask = (const int*)  d_in[1];
    const float* Wq   = (const float*)d_in[2];
    const float* bq   = (const float*)d_in[3];
    const float* Wk   = (const float*)d_in[4];
    const float* bk   = (const float*)d_in[5];
    const float* Wv   = (const float*)d_in[6];
    const float* bv   = (const float*)d_in[7];
    float* out = (float*)d_out;

    fp16 *Xh, *Wqth, *Wqtl, *Wkth, *Wktl, *Wvth, *Wvtl;
    fp16 *Qh, *Khi, *Klo, *Vh, *Vt, *P;
    float *Sc;
    cudaGetSymbolAddress((void**)&Xh, g_Xh);
    cudaGetSymbolAddress((void**)&Wqth, g_Wqt_hi); cudaGetSymbolAddress((void**)&Wqtl, g_Wqt_lo);
    cudaGetSymbolAddress((void**)&Wkth, g_Wkt_hi); cudaGetSymbolAddress((void**)&Wktl, g_Wkt_lo);
    cudaGetSymbolAddress((void**)&Wvth, g_Wvt_hi); cudaGetSymbolAddress((void**)&Wvtl, g_Wvt_lo);
    cudaGetSymbolAddress((void**)&Qh, g_Qh);
    cudaGetSymbolAddress((void**)&Khi, g_Khi);   cudaGetSymbolAddress((void**)&Klo, g_Klo);
    cudaGetSymbolAddress((void**)&Vh, g_Vh);     cudaGetSymbolAddress((void**)&Vt, g_Vt);
    cudaGetSymbolAddress((void**)&P, g_P);
    cudaGetSymbolAddress((void**)&Sc, g_S);

    const int SMEM_P2 = STAGES * (ATILE_B + 2 * TILE_B) + 1024;   // 197632
    const int SMEM_P1 = STAGES * (ATILE_B + 1 * TILE_B) + 1024;   // 148480
    cudaFuncSetAttribute(gemm_split_kernel<1, 2, true>,
                         cudaFuncAttributeMaxDynamicSharedMemorySize, SMEM_P2);
    cudaFuncSetAttribute(gemm_split_kernel<2, 2, true>,
                         cudaFuncAttributeMaxDynamicSharedMemorySize, SMEM_P2);
    cudaFuncSetAttribute(gemm_split_kernel<0, 2, false>,
                         cudaFuncAttributeMaxDynamicSharedMemorySize, SMEM_P2);
    cudaFuncSetAttribute(gemm_split_kernel<0, 1, false>,
                         cudaFuncAttributeMaxDynamicSharedMemorySize, SMEM_P1);

    const float inv32 = 1.0f / 32.0f;

    // 1) round input to fp16
    const long nX = (long)BS * HID;
    round_kernel<<<(unsigned)(nX / 1024), 256>>>(inp, Xh, nX);

    // 2) transpose+split weights (x32):  Wt[n][k] = 32*W[k][n]
    dim3 wgrid(HID / 32, HID / 32), wblk(32, 8);
    wtrans_kernel<<<wgrid, wblk>>>(Wq, Wqth, Wqtl);
    wtrans_kernel<<<wgrid, wblk>>>(Wk, Wkth, Wktl);
    wtrans_kernel<<<wgrid, wblk>>>(Wv, Wvth, Wvtl);

    // 3) QKV projections (2-product): acc*(1/32) + bias.
    //    Q -> single fp16; K -> hi/lo; V -> single fp16
    dim3 gblk(256);
    dim3 g1(HID / 128, BS / 256, 1);
    gemm_split_kernel<2, 2, true><<<g1, gblk, SMEM_P2>>>(
        Xh, Wqth, Wqtl, bq, inv32, nullptr, Qh, nullptr, HID, HID, 0, 0, 0);
    gemm_split_kernel<1, 2, true><<<g1, gblk, SMEM_P2>>>(
        Xh, Wkth, Wktl, bk, inv32, nullptr, Khi, Klo, HID, HID, 0, 0, 0);
    gemm_split_kernel<2, 2, true><<<g1, gblk, SMEM_P2>>>(
        Xh, Wvth, Wvtl, bv, inv32, nullptr, Vh, nullptr, HID, HID, 0, 0, 0);

    // 4) transpose V per batch: [S,H] -> [H,S]
    dim3 tgrid(HID / 32, SEQ / 32, BATCH), tblk(32, 8);
    btrans_kernel<<<tgrid, tblk>>>(Vh, Vt, SEQ, HID);

    // 5) scores = (Q @ K^T)/32 (batched, 2-product), fp32 out
    dim3 g2(SEQ / 128, SEQ / 256, BATCH);
    gemm_split_kernel<0, 2, false><<<g2, gblk, SMEM_P2>>>(
        Qh, Khi, Klo, nullptr, inv32, Sc, nullptr, nullptr,
        HID, SEQ, (long)SEQ * HID, (long)SEQ * HID, (long)SEQ * SEQ);

    // 6) masked softmax -> probs fp16
    softmax_kernel<<<dim3(SEQ, BATCH), 256>>>(Sc, mask, P);

    // 7) out = P @ Vt^T (batched, 1-product), fp32 out
    dim3 g3(HID / 128, SEQ / 256, BATCH);
    gemm_split_kernel<0, 1, false><<<g3, gblk, SMEM_P1>>>(
        P, Vt, nullptr, nullptr, 1.0f, out, nullptr, nullptr,
        SEQ, HID, (long)SEQ * SEQ, (long)SEQ * HID, (long)SEQ * HID);
}

// round 7
// speedup vs baseline: 1.1852x; 1.1852x over previous
#include <cuda_runtime.h>
#include <cuda_fp16.h>
#include <math.h>
#include <stdint.h>

#define BATCH 8
#define SEQ   2048
#define HID   1024
#define BS    (BATCH*SEQ)

typedef __half fp16;

// ---------------------------------------------------------------------------
// Scratch (device globals — allocation is forbidden)
// ---------------------------------------------------------------------------
__device__ fp16 g_Xh[(size_t)BS * HID];
__device__ fp16 g_Wqt_hi[(size_t)HID * HID], g_Wqt_lo[(size_t)HID * HID];
__device__ fp16 g_Wkt_hi[(size_t)HID * HID], g_Wkt_lo[(size_t)HID * HID];
__device__ fp16 g_Wvt_hi[(size_t)HID * HID], g_Wvt_lo[(size_t)HID * HID];
__device__ fp16 g_Qh[(size_t)BS * HID];
__device__ fp16 g_Kh[(size_t)BS * HID];
__device__ fp16 g_Vh[(size_t)BS * HID];
__device__ fp16 g_Vt[(size_t)BS * HID];
__device__ float g_S[(size_t)BATCH * SEQ * SEQ];
__device__ fp16 g_P[(size_t)BATCH * SEQ * SEQ];

// ---------------------------------------------------------------------------
// Helpers
// ---------------------------------------------------------------------------
__device__ __forceinline__ uint32_t smem_u32(const void* p) {
    uint32_t a;
    asm("{ .reg .u64 t; cvta.to.shared.u64 t, %1; cvt.u32.u64 %0, t; }" : "=r"(a) : "l"(p));
    return a;
}

__device__ __forceinline__ void cp_async16(uint32_t dst, const void* src) {
    asm volatile("cp.async.cg.shared.global [%0], [%1], 16;" :: "r"(dst), "l"(src));
}
__device__ __forceinline__ void cp_commit() {
    asm volatile("cp.async.commit_group;");
}
template<int N>
__device__ __forceinline__ void cp_wait() {
    asm volatile("cp.async.wait_group %0;" :: "n"(N));
}

__device__ __forceinline__ void ldsm4(uint32_t* r, uint32_t addr) {
    asm volatile("ldmatrix.sync.aligned.m8n8.x4.shared.b16 {%0,%1,%2,%3}, [%4];"
                 : "=r"(r[0]), "=r"(r[1]), "=r"(r[2]), "=r"(r[3]) : "r"(addr));
}

__device__ __forceinline__ void mma16816(float* d, const uint32_t* a, const uint32_t* b) {
    asm volatile(
        "mma.sync.aligned.m16n8k16.row.col.f32.f16.f16.f32 "
        "{%0,%1,%2,%3}, {%4,%5,%6,%7}, {%8,%9}, {%0,%1,%2,%3};"
        : "+f"(d[0]), "+f"(d[1]), "+f"(d[2]), "+f"(d[3])
        : "r"(a[0]), "r"(a[1]), "r"(a[2]), "r"(a[3]), "r"(b[0]), "r"(b[1]));
}

// SW128 swizzle of a byte offset within a tile of 128-byte rows
__device__ __forceinline__ uint32_t sw128(uint32_t off) {
    return off ^ ((off >> 3) & 0x70);
}

// ---------------------------------------------------------------------------
// Elementwise round: fp32 -> fp16
// ---------------------------------------------------------------------------
__global__ __launch_bounds__(256) void round_kernel(
    const float* __restrict__ x, fp16* __restrict__ h, long n)
{
    long i = ((long)blockIdx.x * 256 + threadIdx.x) * 4;
    if (i >= n) return;
    float4 v = *(const float4*)(x + i);
    *(half2*)(h + i)     = __floats2half2_rn(v.x, v.y);
    *(half2*)(h + i + 2) = __floats2half2_rn(v.z, v.w);
}

// W [K=H, N=H] fp32 -> Wt [N, K] (hi, lo) fp16, scaled by 32 (exact pow2).
// Scaling keeps lo-terms in fp16 normal range; epilogue multiplies by 1/32.
__global__ __launch_bounds__(256) void wtrans_kernel(
    const float* __restrict__ W, fp16* __restrict__ hi, fp16* __restrict__ lo)
{
    __shared__ float t[32][33];
    int tx = threadIdx.x, ty = threadIdx.y;
    int x0 = blockIdx.x * 32, y0 = blockIdx.y * 32;
    #pragma unroll
    for (int r = 0; r < 32; r += 8)
        t[ty + r][tx] = W[(long)(y0 + ty + r) * HID + x0 + tx];
    __syncthreads();
    #pragma unroll
    for (int r = 0; r < 32; r += 8) {
        float v = t[tx][ty + r] * 32.0f;
        long o = (long)(x0 + ty + r) * HID + y0 + tx;
        fp16 h = __float2half_rn(v);
        hi[o] = h;
        lo[o] = __float2half_rn(v - __half2float(h));
    }
}

// fp16 batched transpose: in [R, C] -> out [C, R] per batch (blockIdx.z)
__global__ __launch_bounds__(256) void btrans_kernel(
    const fp16* __restrict__ in, fp16* __restrict__ out, int R, int C)
{
    __shared__ fp16 t[32][33];
    int tx = threadIdx.x, ty = threadIdx.y;
    int x0 = blockIdx.x * 32, y0 = blockIdx.y * 32;
    in  += (long)blockIdx.z * R * C;
    out += (long)blockIdx.z * R * C;
    #pragma unroll
    for (int r = 0; r < 32; r += 8)
        t[ty + r][tx] = in[(long)(y0 + ty + r) * C + x0 + tx];
    __syncthreads();
    #pragma unroll
    for (int r = 0; r < 32; r += 8)
        out[(long)(x0 + ty + r) * R + y0 + tx] = t[tx][ty + r];
}

// ---------------------------------------------------------------------------
// HMMA fp16 GEMM (A single precision-level, B optionally hi/lo split):
//   PRODUCTS==2: C = Ah*(Bhi+Blo)^T   (2 mma products)
//   PRODUCTS==1: C = Ah*Bhi^T
// A: [M,K] K-major.  B: [N,K] K-major.  CTA tile 128x128, BK=64,
// 256 threads (8 warps, 4Mx2N, warp tile 32x64), 3-stage cp.async pipeline.
// OUTMODE: 0 = fp32, 1 = fp16 hi/lo, 2 = fp16 single.
// Epilogue: v = acc*cscale (+ bias).
// ---------------------------------------------------------------------------
#define TILE_B   16384                 // 128 rows x 128 bytes (64 fp16)
#define STAGES   3

// Load one 128x64 fp16 tile (global, row stride ldk elems) into swizzled SMEM.
__device__ __forceinline__ void load_tile_async(
    uint32_t dst, const fp16* __restrict__ src, int ldk, int tid)
{
    #pragma unroll
    for (int i = 0; i < 4; i++) {
        int s = tid + i * 256;
        int row = s >> 3, seg = s & 7;
        uint32_t off = row * 128 + seg * 16;
        cp_async16(dst + sw128(off), src + (long)row * ldk + seg * 8);
    }
}

template<int OUTMODE, int PRODUCTS, bool ADD_BIAS>
__global__ __launch_bounds__(256, 1) void gemm_split_kernel(
    const fp16* __restrict__ Ah,
    const fp16* __restrict__ Bhi, const fp16* __restrict__ Blo,
    const float* __restrict__ bias, float cscale,
    float* __restrict__ Cf, fp16* __restrict__ Chi, fp16* __restrict__ Clo,
    int K, int Ncols, long sA, long sB, long sC)
{
    constexpr int NT = (PRODUCTS == 2) ? 3 : 2;
    constexpr uint32_t STAGE_B = NT * TILE_B;
    constexpr uint32_t OFF_A   = 0;
    constexpr uint32_t OFF_BHI = 1 * TILE_B;
    constexpr uint32_t OFF_BLO = 2 * TILE_B;                 // P2 only

    extern __shared__ char smem[];
    const uint32_t tiles = (smem_u32(smem) + 1023) & ~1023u;

    const int tid = threadIdx.x;
    const int lane = tid & 31;
    const int w = tid >> 5;
    const int wm = w & 3;          // 0..3 : 32-row band
    const int wn = w >> 2;         // 0..1 : 64-col band
    const int bn = blockIdx.x, bm = blockIdx.y, bz = blockIdx.z;

    Ah  += bz * sA + (long)(bm * 128) * K;
    Bhi += bz * sB + (long)(bn * 128) * K;
    if (PRODUCTS == 2) Blo += bz * sB + (long)(bn * 128) * K;

    float acc[2][8][4];
    #pragma unroll
    for (int mt = 0; mt < 2; mt++)
        #pragma unroll
        for (int nt = 0; nt < 8; nt++)
            #pragma unroll
            for (int r = 0; r < 4; r++) acc[mt][nt][r] = 0.f;

    const int nchunks = K / 64;

    auto issue_chunk = [&](int cc) {
        const uint32_t buf = tiles + (uint32_t)(cc % STAGES) * STAGE_B;
        const long k0 = (long)cc * 64;
        load_tile_async(buf + OFF_A, Ah + k0, K, tid);
        load_tile_async(buf + OFF_BHI, Bhi + k0, K, tid);
        if (PRODUCTS == 2) load_tile_async(buf + OFF_BLO, Blo + k0, K, tid);
        cp_commit();
    };

    // prologue: stages 0,1
    issue_chunk(0);
    issue_chunk(1);

    // ldmatrix base offsets (within a tile)
    const int arow = wm * 32 + (lane & 15);            // +mt*16
    const int brow = wn * 64 + (lane & 15);            // +nt2*16
    const uint32_t kseg = (lane >> 4) * 16;            // 16B half-select

    for (int c = 0; c < nchunks; c++) {
        if (c + 2 < nchunks) { issue_chunk(c + 2); cp_wait<2>(); }
        else if (c + 1 < nchunks) { cp_wait<1>(); }
        else { cp_wait<0>(); }
        __syncthreads();

        const uint32_t buf = tiles + (uint32_t)(c % STAGES) * STAGE_B;
        const uint32_t As   = buf + OFF_A;
        const uint32_t Bs_h = buf + OFF_BHI;
        const uint32_t Bs_l = buf + OFF_BLO;

        #pragma unroll
        for (int ks = 0; ks < 4; ks++) {
            const uint32_t kb = ks * 32 + kseg;   // byte col within 128B row
            uint32_t ah[2][4];
            #pragma unroll
            for (int mt = 0; mt < 2; mt++) {
                uint32_t off = (uint32_t)(arow + mt * 16) * 128 + kb;
                ldsm4(ah[mt], As + sw128(off));
            }
            #pragma unroll
            for (int nt2 = 0; nt2 < 4; nt2++) {
                uint32_t off = (uint32_t)(brow + nt2 * 16) * 128 + kb;
                uint32_t sw = sw128(off);
                uint32_t rh[4];
                ldsm4(rh, Bs_h + sw);
                uint32_t b0h[2] = {rh[0], rh[2]}, b1h[2] = {rh[1], rh[3]};
                // interleave accumulators: reuse distance 4
                mma16816(acc[0][nt2 * 2 + 0], ah[0], b0h);
                mma16816(acc[0][nt2 * 2 + 1], ah[0], b1h);
                mma16816(acc[1][nt2 * 2 + 0], ah[1], b0h);
                mma16816(acc[1][nt2 * 2 + 1], ah[1], b1h);
                if (PRODUCTS == 2) {
                    uint32_t rl[4];
                    ldsm4(rl, Bs_l + sw);
                    uint32_t b0l[2] = {rl[0], rl[2]}, b1l[2] = {rl[1], rl[3]};
                    mma16816(acc[0][nt2 * 2 + 0], ah[0], b0l);
                    mma16816(acc[0][nt2 * 2 + 1], ah[0], b1l);
                    mma16816(acc[1][nt2 * 2 + 0], ah[1], b0l);
                    mma16816(acc[1][nt2 * 2 + 1], ah[1], b1l);
                }
            }
        }
        __syncthreads();
    }

    // ---- epilogue ----
    const int qr = lane >> 2;      // 0..7
    const int qc = lane & 3;       // 0..3
    #pragma unroll
    for (int mt = 0; mt < 2; mt++) {
        #pragma unroll
        for (int half_ = 0; half_ < 2; half_++) {   // d0,d1 vs d2,d3 (row, row+8)
            const long row = (long)(bm * 128 + wm * 32 + mt * 16 + qr + half_ * 8);
            const long cb = bz * sC + row * Ncols;
            #pragma unroll
            for (int nt = 0; nt < 8; nt++) {
                const int col = bn * 128 + wn * 64 + nt * 8 + qc * 2;
                float v0 = acc[mt][nt][half_ * 2 + 0] * cscale;
                float v1 = acc[mt][nt][half_ * 2 + 1] * cscale;
                if constexpr (ADD_BIAS) { v0 += bias[col]; v1 += bias[col + 1]; }
                if constexpr (OUTMODE == 0) {
                    *(float2*)(Cf + cb + col) = make_float2(v0, v1);
                } else if constexpr (OUTMODE == 1) {
                    fp16 h0 = __float2half_rn(v0);
                    fp16 h1 = __float2half_rn(v1);
                    fp16 l0 = __float2half_rn(v0 - __half2float(h0));
                    fp16 l1 = __float2half_rn(v1 - __half2float(h1));
                    *(half2*)(Chi + cb + col) = __halves2half2(h0, h1);
                    *(half2*)(Clo + cb + col) = __halves2half2(l0, l1);
                } else {
                    *(half2*)(Chi + cb + col) = __floats2half2_rn(v0, v1);
                }
            }
        }
    }
}

// ---------------------------------------------------------------------------
// Softmax over rows of scores [B,S,S] (already scaled by 1/32 in QK epilogue).
// Single global read (row cached in smem); emits probs as single fp16.
// ---------------------------------------------------------------------------
__global__ __launch_bounds__(256) void softmax_kernel(
    const float* __restrict__ S, const int* __restrict__ mask, fp16* __restrict__ P)
{
    const int row = blockIdx.x;
    const int b   = blockIdx.y;
    const long off = ((long)b * SEQ + row) * SEQ;
    const float* ptr = S + off;
    const int* mrow = mask + (long)b * SEQ;
    const int tid = threadIdx.x;

    __shared__ float buf[SEQ];
    __shared__ float red[256];

    float m = -INFINITY;
    #pragma unroll
    for (int k = tid * 4; k < SEQ; k += 1024) {
        float4 s = *(const float4*)(ptr + k);
        int4 mk = *(const int4*)(mrow + k);
        s.x = (mk.x == 0) ? -INFINITY : s.x;
        s.y = (mk.y == 0) ? -INFINITY : s.y;
        s.z = (mk.z == 0) ? -INFINITY : s.z;
        s.w = (mk.w == 0) ? -INFINITY : s.w;
        *(float4*)(buf + k) = s;
        m = fmaxf(m, fmaxf(fmaxf(s.x, s.y), fmaxf(s.z, s.w)));
    }
    red[tid] = m; __syncthreads();
    for (int o = 128; o > 0; o >>= 1) {
        if (tid < o) red[tid] = fmaxf(red[tid], red[tid + o]);
        __syncthreads();
    }
    m = red[0];
    __syncthreads();

    float sum = 0.f;
    #pragma unroll
    for (int k = tid * 4; k < SEQ; k += 1024) {
        float4 s = *(float4*)(buf + k);
        s.x = __expf(s.x - m); s.y = __expf(s.y - m);
        s.z = __expf(s.z - m); s.w = __expf(s.w - m);
        *(float4*)(buf + k) = s;
        sum += s.x + s.y + s.z + s.w;
    }
    red[tid] = sum; __syncthreads();
    for (int o = 128; o > 0; o >>= 1) {
        if (tid < o) red[tid] += red[tid + o];
        __syncthreads();
    }
    const float inv = 1.f / red[0];

    #pragma unroll
    for (int k = tid * 4; k < SEQ; k += 1024) {
        float4 e = *(float4*)(buf + k);
        *(half2*)(P + off + k)     = __floats2half2_rn(e.x * inv, e.y * inv);
        *(half2*)(P + off + k + 2) = __floats2half2_rn(e.z * inv, e.w * inv);
    }
}

// ---------------------------------------------------------------------------
extern "C" void kernel_launch(void* const* d_in, const int* in_sizes, int n_in,
                              void* d_out, int out_size)
{
    const float* inp  = (const float*)d_in[0];
    const int*   mask = (const int*)  d_in[1];
    const float* Wq   = (const float*)d_in[2];
    const float* bq   = (const float*)d_in[3];
    const float* Wk   = (const float*)d_in[4];
    const float* bk   = (const float*)d_in[5];
    const float* Wv   = (const float*)d_in[6];
    const float* bv   = (const float*)d_in[7];
    float* out = (float*)d_out;

    fp16 *Xh, *Wqth, *Wqtl, *Wkth, *Wktl, *Wvth, *Wvtl;
    fp16 *Qh, *Kh, *Vh, *Vt, *P;
    float *Sc;
    cudaGetSymbolAddress((void**)&Xh, g_Xh);
    cudaGetSymbolAddress((void**)&Wqth, g_Wqt_hi); cudaGetSymbolAddress((void**)&Wqtl, g_Wqt_lo);
    cudaGetSymbolAddress((void**)&Wkth, g_Wkt_hi); cudaGetSymbolAddress((void**)&Wktl, g_Wkt_lo);
    cudaGetSymbolAddress((void**)&Wvth, g_Wvt_hi); cudaGetSymbolAddress((void**)&Wvtl, g_Wvt_lo);
    cudaGetSymbolAddress((void**)&Qh, g_Qh);
    cudaGetSymbolAddress((void**)&Kh, g_Kh);
    cudaGetSymbolAddress((void**)&Vh, g_Vh);     cudaGetSymbolAddress((void**)&Vt, g_Vt);
    cudaGetSymbolAddress((void**)&P, g_P);
    cudaGetSymbolAddress((void**)&Sc, g_S);

    const int SMEM_P2 = STAGES * 3 * TILE_B + 1024;   // 148480
    const int SMEM_P1 = STAGES * 2 * TILE_B + 1024;   // 99328
    cudaFuncSetAttribute(gemm_split_kernel<2, 2, true>,
                         cudaFuncAttributeMaxDynamicSharedMemorySize, SMEM_P2);
    cudaFuncSetAttribute(gemm_split_kernel<0, 1, false>,
                         cudaFuncAttributeMaxDynamicSharedMemorySize, SMEM_P1);

    const float inv32 = 1.0f / 32.0f;

    // 1) round input to fp16
    const long nX = (long)BS * HID;
    round_kernel<<<(unsigned)(nX / 1024), 256>>>(inp, Xh, nX);

    // 2) transpose+split weights (x32):  Wt[n][k] = 32*W[k][n]
    dim3 wgrid(HID / 32, HID / 32), wblk(32, 8);
    wtrans_kernel<<<wgrid, wblk>>>(Wq, Wqth, Wqtl);
    wtrans_kernel<<<wgrid, wblk>>>(Wk, Wkth, Wktl);
    wtrans_kernel<<<wgrid, wblk>>>(Wv, Wvth, Wvtl);

    // 3) QKV projections (2-product): acc*(1/32) + bias.  All -> single fp16
    dim3 gblk(256);
    dim3 g1(HID / 128, BS / 128, 1);
    gemm_split_kernel<2, 2, true><<<g1, gblk, SMEM_P2>>>(
        Xh, Wqth, Wqtl, bq, inv32, nullptr, Qh, nullptr, HID, HID, 0, 0, 0);
    gemm_split_kernel<2, 2, true><<<g1, gblk, SMEM_P2>>>(
        Xh, Wkth, Wktl, bk, inv32, nullptr, Kh, nullptr, HID, HID, 0, 0, 0);
    gemm_split_kernel<2, 2, true><<<g1, gblk, SMEM_P2>>>(
        Xh, Wvth, Wvtl, bv, inv32, nullptr, Vh, nullptr, HID, HID, 0, 0, 0);

    // 4) transpose V per batch: [S,H] -> [H,S]
    dim3 tgrid(HID / 32, SEQ / 32, BATCH), tblk(32, 8);
    btrans_kernel<<<tgrid, tblk>>>(Vh, Vt, SEQ, HID);

    // 5) scores = (Q @ K^T)/32 (batched, 1-product), fp32 out
    dim3 g2(SEQ / 128, SEQ / 128, BATCH);
    gemm_split_kernel<0, 1, false><<<g2, gblk, SMEM_P1>>>(
        Qh, Kh, nullptr, nullptr, inv32, Sc, nullptr, nullptr,
        HID, SEQ, (long)SEQ * HID, (long)SEQ * HID, (long)SEQ * SEQ);

    // 6) masked softmax -> probs fp16
    softmax_kernel<<<dim3(SEQ, BATCH), 256>>>(Sc, mask, P);

    // 7) out = P @ Vt^T (batched, 1-product), fp32 out
    dim3 g3(HID / 128, SEQ / 128, BATCH);
    gemm_split_kernel<0, 1, false><<<g3, gblk, SMEM_P1>>>(
        P, Vt, nullptr, nullptr, 1.0f, out, nullptr, nullptr,
        SEQ, HID, (long)SEQ * SEQ, (long)SEQ * HID, (long)SEQ * HID);
}

// round 8
// speedup vs baseline: 1.7309x; 1.4605x over previous
#include <cuda_runtime.h>
#include <cuda_fp16.h>
#include <math.h>
#include <stdint.h>

#define BATCH 8
#define SEQ   2048
#define HID   1024
#define BS    (BATCH*SEQ)

typedef __half fp16;

// ---------------------------------------------------------------------------
// Scratch (device globals — allocation is forbidden)
// ---------------------------------------------------------------------------
__device__ fp16 g_Xh[(size_t)BS * HID];
__device__ fp16 g_Wt[3 * (size_t)HID * HID];   // q,k,v transposed, x32, fp16
__device__ fp16 g_Qh[(size_t)BS * HID];
__device__ fp16 g_Kh[(size_t)BS * HID];
__device__ fp16 g_Vh[(size_t)BS * HID];
__device__ fp16 g_Vt[(size_t)BS * HID];
__device__ float g_S[(size_t)BATCH * SEQ * SEQ];
__device__ fp16 g_P[(size_t)BATCH * SEQ * SEQ];

// ---------------------------------------------------------------------------
// Helpers
// ---------------------------------------------------------------------------
__device__ __forceinline__ uint32_t smem_u32(const void* p) {
    uint32_t a;
    asm("{ .reg .u64 t; cvta.to.shared.u64 t, %1; cvt.u32.u64 %0, t; }" : "=r"(a) : "l"(p));
    return a;
}

__device__ __forceinline__ void cp_async16(uint32_t dst, const void* src) {
    asm volatile("cp.async.cg.shared.global [%0], [%1], 16;" :: "r"(dst), "l"(src));
}
__device__ __forceinline__ void cp_commit() {
    asm volatile("cp.async.commit_group;");
}
template<int N>
__device__ __forceinline__ void cp_wait() {
    asm volatile("cp.async.wait_group %0;" :: "n"(N));
}

__device__ __forceinline__ void ldsm4(uint32_t* r, uint32_t addr) {
    asm volatile("ldmatrix.sync.aligned.m8n8.x4.shared.b16 {%0,%1,%2,%3}, [%4];"
                 : "=r"(r[0]), "=r"(r[1]), "=r"(r[2]), "=r"(r[3]) : "r"(addr));
}

__device__ __forceinline__ void mma16816(float* d, const uint32_t* a, const uint32_t* b) {
    asm volatile(
        "mma.sync.aligned.m16n8k16.row.col.f32.f16.f16.f32 "
        "{%0,%1,%2,%3}, {%4,%5,%6,%7}, {%8,%9}, {%0,%1,%2,%3};"
        : "+f"(d[0]), "+f"(d[1]), "+f"(d[2]), "+f"(d[3])
        : "r"(a[0]), "r"(a[1]), "r"(a[2]), "r"(a[3]), "r"(b[0]), "r"(b[1]));
}

// SW128 swizzle of a byte offset within a tile of 128-byte rows
__device__ __forceinline__ uint32_t sw128(uint32_t off) {
    return off ^ ((off >> 3) & 0x70);
}

// ---------------------------------------------------------------------------
// Elementwise round: fp32 -> fp16
// ---------------------------------------------------------------------------
__global__ __launch_bounds__(256) void round_kernel(
    const float* __restrict__ x, fp16* __restrict__ h, long n)
{
    long i = ((long)blockIdx.x * 256 + threadIdx.x) * 4;
    if (i >= n) return;
    float4 v = *(const float4*)(x + i);
    *(half2*)(h + i)     = __floats2half2_rn(v.x, v.y);
    *(half2*)(h + i + 2) = __floats2half2_rn(v.z, v.w);
}

// W [K=H, N=H] fp32 -> Wt [N, K] fp16, scaled by 32 (exact pow2).
__global__ __launch_bounds__(256) void wtrans_kernel(
    const float* __restrict__ W, fp16* __restrict__ out)
{
    __shared__ float t[32][33];
    int tx = threadIdx.x, ty = threadIdx.y;
    int x0 = blockIdx.x * 32, y0 = blockIdx.y * 32;
    #pragma unroll
    for (int r = 0; r < 32; r += 8)
        t[ty + r][tx] = W[(long)(y0 + ty + r) * HID + x0 + tx];
    __syncthreads();
    #pragma unroll
    for (int r = 0; r < 32; r += 8)
        out[(long)(x0 + ty + r) * HID + y0 + tx] = __float2half_rn(t[tx][ty + r] * 32.0f);
}

// fp16 batched transpose: in [R, C] -> out [C, R] per batch (blockIdx.z)
__global__ __launch_bounds__(256) void btrans_kernel(
    const fp16* __restrict__ in, fp16* __restrict__ out, int R, int C)
{
    __shared__ fp16 t[32][33];
    int tx = threadIdx.x, ty = threadIdx.y;
    int x0 = blockIdx.x * 32, y0 = blockIdx.y * 32;
    in  += (long)blockIdx.z * R * C;
    out += (long)blockIdx.z * R * C;
    #pragma unroll
    for (int r = 0; r < 32; r += 8)
        t[ty + r][tx] = in[(long)(y0 + ty + r) * C + x0 + tx];
    __syncthreads();
    #pragma unroll
    for (int r = 0; r < 32; r += 8)
        out[(long)(x0 + ty + r) * R + y0 + tx] = t[tx][ty + r];
}

// ---------------------------------------------------------------------------
// Shared HMMA mainloop pieces: CTA tile 128x128, BK=64, 256 threads
// (8 warps, 4Mx2N, warp tile 32x64), 3-stage cp.async pipeline.
// ---------------------------------------------------------------------------
#define TILE_B   16384                 // 128 rows x 128 bytes (64 fp16)
#define STAGES   3
#define SMEM_GEMM (STAGES * 2 * TILE_B + 1024)   // 99328

// Load one 128x64 fp16 tile (global, row stride ldk elems) into swizzled SMEM.
__device__ __forceinline__ void load_tile_async(
    uint32_t dst, const fp16* __restrict__ src, int ldk, int tid)
{
    #pragma unroll
    for (int i = 0; i < 4; i++) {
        int s = tid + i * 256;
        int row = s >> 3, seg = s & 7;
        uint32_t off = row * 128 + seg * 16;
        cp_async16(dst + sw128(off), src + (long)row * ldk + seg * 8);
    }
}

// Mainloop: accumulates Ah * Bh^T over K into acc. Runs full pipeline.
__device__ __forceinline__ void gemm_mainloop_p1(
    uint32_t tiles, const fp16* Ah, const fp16* Bh, int K, int tid,
    float acc[2][8][4])
{
    const int lane = tid & 31;
    const int w = tid >> 5;
    const int wm = w & 3, wn = w >> 2;
    const int nchunks = K / 64;

    auto issue_chunk = [&](int cc) {
        const uint32_t buf = tiles + (uint32_t)(cc % STAGES) * (2 * TILE_B);
        const long k0 = (long)cc * 64;
        load_tile_async(buf, Ah + k0, K, tid);
        load_tile_async(buf + TILE_B, Bh + k0, K, tid);
        cp_commit();
    };
    issue_chunk(0);
    issue_chunk(1);

    const int arow = wm * 32 + (lane & 15);
    const int brow = wn * 64 + (lane & 15);
    const uint32_t kseg = (lane >> 4) * 16;

    for (int c = 0; c < nchunks; c++) {
        if (c + 2 < nchunks) { issue_chunk(c + 2); cp_wait<2>(); }
        else if (c + 1 < nchunks) { cp_wait<1>(); }
        else { cp_wait<0>(); }
        __syncthreads();

        const uint32_t buf = tiles + (uint32_t)(c % STAGES) * (2 * TILE_B);
        const uint32_t As = buf;
        const uint32_t Bs = buf + TILE_B;

        #pragma unroll
        for (int ks = 0; ks < 4; ks++) {
            const uint32_t kb = ks * 32 + kseg;
            uint32_t ah[2][4];
            #pragma unroll
            for (int mt = 0; mt < 2; mt++) {
                uint32_t off = (uint32_t)(arow + mt * 16) * 128 + kb;
                ldsm4(ah[mt], As + sw128(off));
            }
            #pragma unroll
            for (int nt2 = 0; nt2 < 4; nt2++) {
                uint32_t off = (uint32_t)(brow + nt2 * 16) * 128 + kb;
                uint32_t rh[4];
                ldsm4(rh, Bs + sw128(off));
                uint32_t b0h[2] = {rh[0], rh[2]}, b1h[2] = {rh[1], rh[3]};
                mma16816(acc[0][nt2 * 2 + 0], ah[0], b0h);
                mma16816(acc[0][nt2 * 2 + 1], ah[0], b1h);
                mma16816(acc[1][nt2 * 2 + 0], ah[1], b0h);
                mma16816(acc[1][nt2 * 2 + 1], ah[1], b1h);
            }
        }
        __syncthreads();
    }
}

// ---------------------------------------------------------------------------
// Fused QKV projection: grid.z in {0,1,2} selects (W, bias, out).
// out[z] = fp16( (Xh @ Wt[z]^T) / 32 + bias[z] )
// ---------------------------------------------------------------------------
struct QKVArgs {
    const fp16* W;         // g_Wt base (3 weights, contiguous)
    const float* b[3];
    fp16* out[3];
};

__global__ __launch_bounds__(256) void qkv_kernel(
    const fp16* __restrict__ Xh, QKVArgs args)
{
    extern __shared__ char smem[];
    const uint32_t tiles = (smem_u32(smem) + 1023) & ~1023u;

    const int tid = threadIdx.x;
    const int lane = tid & 31;
    const int w = tid >> 5;
    const int wm = w & 3, wn = w >> 2;
    const int bn = blockIdx.x, bm = blockIdx.y, bz = blockIdx.z;

    const fp16* Ah = Xh + (long)(bm * 128) * HID;
    const fp16* Bh = args.W + (size_t)bz * HID * HID + (long)(bn * 128) * HID;
    const float* bias = args.b[bz];
    fp16* out = args.out[bz];

    float acc[2][8][4];
    #pragma unroll
    for (int mt = 0; mt < 2; mt++)
        #pragma unroll
        for (int nt = 0; nt < 8; nt++)
            #pragma unroll
            for (int r = 0; r < 4; r++) acc[mt][nt][r] = 0.f;

    gemm_mainloop_p1(tiles, Ah, Bh, HID, tid, acc);

    const int qr = lane >> 2, qc = lane & 3;
    #pragma unroll
    for (int mt = 0; mt < 2; mt++)
        #pragma unroll
        for (int half_ = 0; half_ < 2; half_++) {
            const long row = (long)(bm * 128 + wm * 32 + mt * 16 + qr + half_ * 8);
            const long cb = row * HID;
            #pragma unroll
            for (int nt = 0; nt < 8; nt++) {
                const int col = bn * 128 + wn * 64 + nt * 8 + qc * 2;
                float v0 = acc[mt][nt][half_ * 2 + 0] * (1.0f / 32.0f) + bias[col];
                float v1 = acc[mt][nt][half_ * 2 + 1] * (1.0f / 32.0f) + bias[col + 1];
                *(half2*)(out + cb + col) = __floats2half2_rn(v0, v1);
            }
        }
}

// ---------------------------------------------------------------------------
// Generic 1-product GEMM, fp32 out: C = (Ah @ Bh^T) * cscale
// ---------------------------------------------------------------------------
__global__ __launch_bounds__(256) void gemm_p1_kernel(
    const fp16* __restrict__ Ah, const fp16* __restrict__ Bh, float cscale,
    float* __restrict__ Cf, int K, int Ncols, long sA, long sB, long sC)
{
    extern __shared__ char smem[];
    const uint32_t tiles = (smem_u32(smem) + 1023) & ~1023u;

    const int tid = threadIdx.x;
    const int lane = tid & 31;
    const int w = tid >> 5;
    const int wm = w & 3, wn = w >> 2;
    const int bn = blockIdx.x, bm = blockIdx.y, bz = blockIdx.z;

    Ah += bz * sA + (long)(bm * 128) * K;
    Bh += bz * sB + (long)(bn * 128) * K;

    float acc[2][8][4];
    #pragma unroll
    for (int mt = 0; mt < 2; mt++)
        #pragma unroll
        for (int nt = 0; nt < 8; nt++)
            #pragma unroll
            for (int r = 0; r < 4; r++) acc[mt][nt][r] = 0.f;

    gemm_mainloop_p1(tiles, Ah, Bh, K, tid, acc);

    const int qr = lane >> 2, qc = lane & 3;
    #pragma unroll
    for (int mt = 0; mt < 2; mt++)
        #pragma unroll
        for (int half_ = 0; half_ < 2; half_++) {
            const long row = (long)(bm * 128 + wm * 32 + mt * 16 + qr + half_ * 8);
            const long cb = bz * sC + row * Ncols;
            #pragma unroll
            for (int nt = 0; nt < 8; nt++) {
                const int col = bn * 128 + wn * 64 + nt * 8 + qc * 2;
                float v0 = acc[mt][nt][half_ * 2 + 0] * cscale;
                float v1 = acc[mt][nt][half_ * 2 + 1] * cscale;
                *(float2*)(Cf + cb + col) = make_float2(v0, v1);
            }
        }
}

// ---------------------------------------------------------------------------
// Softmax over rows of scores [B,S,S] (already scaled by 1/32 in QK epilogue).
// Single global read (row cached in smem); emits probs as single fp16.
// ---------------------------------------------------------------------------
__global__ __launch_bounds__(256) void softmax_kernel(
    const float* __restrict__ S, const int* __restrict__ mask, fp16* __restrict__ P)
{
    const int row = blockIdx.x;
    const int b   = blockIdx.y;
    const long off = ((long)b * SEQ + row) * SEQ;
    const float* ptr = S + off;
    const int* mrow = mask + (long)b * SEQ;
    const int tid = threadIdx.x;

    __shared__ float buf[SEQ];
    __shared__ float red[256];

    float m = -INFINITY;
    #pragma unroll
    for (int k = tid * 4; k < SEQ; k += 1024) {
        float4 s = *(const float4*)(ptr + k);
        int4 mk = *(const int4*)(mrow + k);
        s.x = (mk.x == 0) ? -INFINITY : s.x;
        s.y = (mk.y == 0) ? -INFINITY : s.y;
        s.z = (mk.z == 0) ? -INFINITY : s.z;
        s.w = (mk.w == 0) ? -INFINITY : s.w;
        *(float4*)(buf + k) = s;
        m = fmaxf(m, fmaxf(fmaxf(s.x, s.y), fmaxf(s.z, s.w)));
    }
    red[tid] = m; __syncthreads();
    for (int o = 128; o > 0; o >>= 1) {
        if (tid < o) red[tid] = fmaxf(red[tid], red[tid + o]);
        __syncthreads();
    }
    m = red[0];
    __syncthreads();

    float sum = 0.f;
    #pragma unroll
    for (int k = tid * 4; k < SEQ; k += 1024) {
        float4 s = *(float4*)(buf + k);
        s.x = __expf(s.x - m); s.y = __expf(s.y - m);
        s.z = __expf(s.z - m); s.w = __expf(s.w - m);
        *(float4*)(buf + k) = s;
        sum += s.x + s.y + s.z + s.w;
    }
    red[tid] = sum; __syncthreads();
    for (int o = 128; o > 0; o >>= 1) {
        if (tid < o) red[tid] += red[tid + o];
        __syncthreads();
    }
    const float inv = 1.f / red[0];

    #pragma unroll
    for (int k = tid * 4; k < SEQ; k += 1024) {
        float4 e = *(float4*)(buf + k);
        *(half2*)(P + off + k)     = __floats2half2_rn(e.x * inv, e.y * inv);
        *(half2*)(P + off + k + 2) = __floats2half2_rn(e.z * inv, e.w * inv);
    }
}

// ---------------------------------------------------------------------------
extern "C" void kernel_launch(void* const* d_in, const int* in_sizes, int n_in,
                              void* d_out, int out_size)
{
    const float* inp  = (const float*)d_in[0];
    const int*   mask = (const int*)  d_in[1];
    const float* Wq   = (const float*)d_in[2];
    const float* bq   = (const float*)d_in[3];
    const float* Wk   = (const float*)d_in[4];
    const float* bk   = (const float*)d_in[5];
    const float* Wv   = (const float*)d_in[6];
    const float* bv   = (const float*)d_in[7];
    float* out = (float*)d_out;

    fp16 *Xh, *Wt, *Qh, *Kh, *Vh, *Vt, *P;
    float *Sc;
    cudaGetSymbolAddress((void**)&Xh, g_Xh);
    cudaGetSymbolAddress((void**)&Wt, g_Wt);
    cudaGetSymbolAddress((void**)&Qh, g_Qh);
    cudaGetSymbolAddress((void**)&Kh, g_Kh);
    cudaGetSymbolAddress((void**)&Vh, g_Vh);
    cudaGetSymbolAddress((void**)&Vt, g_Vt);
    cudaGetSymbolAddress((void**)&P, g_P);
    cudaGetSymbolAddress((void**)&Sc, g_S);

    cudaFuncSetAttribute(qkv_kernel,
                         cudaFuncAttributeMaxDynamicSharedMemorySize, SMEM_GEMM);
    cudaFuncSetAttribute(gemm_p1_kernel,
                         cudaFuncAttributeMaxDynamicSharedMemorySize, SMEM_GEMM);

    // 1) round input to fp16
    const long nX = (long)BS * HID;
    round_kernel<<<(unsigned)(nX / 1024), 256>>>(inp, Xh, nX);

    // 2) transpose weights (x32) into contiguous fp16 buffer
    dim3 wgrid(HID / 32, HID / 32), wblk(32, 8);
    wtrans_kernel<<<wgrid, wblk>>>(Wq, Wt + 0 * (size_t)HID * HID);
    wtrans_kernel<<<wgrid, wblk>>>(Wk, Wt + 1 * (size_t)HID * HID);
    wtrans_kernel<<<wgrid, wblk>>>(Wv, Wt + 2 * (size_t)HID * HID);

    // 3) fused QKV projections (1-product each): z in {Q,K,V}
    QKVArgs qa;
    qa.W = Wt;
    qa.b[0] = bq;  qa.b[1] = bk;  qa.b[2] = bv;
    qa.out[0] = Qh; qa.out[1] = Kh; qa.out[2] = Vh;
    dim3 gblk(256);
    dim3 g1(HID / 128, BS / 128, 3);
    qkv_kernel<<<g1, gblk, SMEM_GEMM>>>(Xh, qa);

    // 4) transpose V per batch: [S,H] -> [H,S]
    dim3 tgrid(HID / 32, SEQ / 32, BATCH), tblk(32, 8);
    btrans_kernel<<<tgrid, tblk>>>(Vh, Vt, SEQ, HID);

    // 5) scores = (Q @ K^T)/32 (batched, 1-product), fp32 out
    dim3 g2(SEQ / 128, SEQ / 128, BATCH);
    gemm_p1_kernel<<<g2, gblk, SMEM_GEMM>>>(
        Qh, Kh, 1.0f / 32.0f, Sc,
        HID, SEQ, (long)SEQ * HID, (long)SEQ * HID, (long)SEQ * SEQ);

    // 6) masked softmax -> probs fp16
    softmax_kernel<<<dim3(SEQ, BATCH), 256>>>(Sc, mask, P);

    // 7) out = P @ Vt^T (batched, 1-product), fp32 out
    dim3 g3(HID / 128, SEQ / 128, BATCH);
    gemm_p1_kernel<<<g3, gblk, SMEM_GEMM>>>(
        P, Vt, 1.0f, out,
        SEQ, HID, (long)SEQ * SEQ, (long)SEQ * HID, (long)SEQ * HID);
}

// round 9
// speedup vs baseline: 1.7408x; 1.0057x over previous
#include <cuda_runtime.h>
#include <cuda_fp16.h>
#include <math.h>
#include <stdint.h>

#define BATCH 8
#define SEQ   2048
#define HID   1024
#define BS    (BATCH*SEQ)

typedef __half fp16;

// ---------------------------------------------------------------------------
// Scratch (device globals — allocation is forbidden)
// ---------------------------------------------------------------------------
__device__ fp16 g_Xh[(size_t)BS * HID];
__device__ fp16 g_Wt[3 * (size_t)HID * HID];   // q,k,v transposed, x32, fp16
__device__ fp16 g_Qh[(size_t)BS * HID];
__device__ fp16 g_Kh[(size_t)BS * HID];
__device__ fp16 g_Vt[(size_t)BS * HID];        // [batch][H][S]
__device__ float g_S[(size_t)BATCH * SEQ * SEQ];
__device__ fp16 g_P[(size_t)BATCH * SEQ * SEQ];

// ---------------------------------------------------------------------------
// Helpers
// ---------------------------------------------------------------------------
__device__ __forceinline__ uint32_t smem_u32(const void* p) {
    uint32_t a;
    asm("{ .reg .u64 t; cvta.to.shared.u64 t, %1; cvt.u32.u64 %0, t; }" : "=r"(a) : "l"(p));
    return a;
}

__device__ __forceinline__ void cp_async16(uint32_t dst, const void* src) {
    asm volatile("cp.async.cg.shared.global [%0], [%1], 16;" :: "r"(dst), "l"(src));
}
__device__ __forceinline__ void cp_commit() {
    asm volatile("cp.async.commit_group;");
}
template<int N>
__device__ __forceinline__ void cp_wait() {
    asm volatile("cp.async.wait_group %0;" :: "n"(N));
}

__device__ __forceinline__ void ldsm4(uint32_t* r, uint32_t addr) {
    asm volatile("ldmatrix.sync.aligned.m8n8.x4.shared.b16 {%0,%1,%2,%3}, [%4];"
                 : "=r"(r[0]), "=r"(r[1]), "=r"(r[2]), "=r"(r[3]) : "r"(addr));
}

__device__ __forceinline__ void mma16816(float* d, const uint32_t* a, const uint32_t* b) {
    asm volatile(
        "mma.sync.aligned.m16n8k16.row.col.f32.f16.f16.f32 "
        "{%0,%1,%2,%3}, {%4,%5,%6,%7}, {%8,%9}, {%0,%1,%2,%3};"
        : "+f"(d[0]), "+f"(d[1]), "+f"(d[2]), "+f"(d[3])
        : "r"(a[0]), "r"(a[1]), "r"(a[2]), "r"(a[3]), "r"(b[0]), "r"(b[1]));
}

// SW128 swizzle of a byte offset within a tile of 128-byte rows
__device__ __forceinline__ uint32_t sw128(uint32_t off) {
    return off ^ ((off >> 3) & 0x70);
}

// ---------------------------------------------------------------------------
// Elementwise round: fp32 -> fp16
// ---------------------------------------------------------------------------
__global__ __launch_bounds__(256) void round_kernel(
    const float* __restrict__ x, fp16* __restrict__ h, long n)
{
    long i = ((long)blockIdx.x * 256 + threadIdx.x) * 4;
    if (i >= n) return;
    float4 v = *(const float4*)(x + i);
    *(half2*)(h + i)     = __floats2half2_rn(v.x, v.y);
    *(half2*)(h + i + 2) = __floats2half2_rn(v.z, v.w);
}

// W [K=H, N=H] fp32 -> Wt [N, K] fp16, scaled by 32 (exact pow2).
// grid.z selects which of the 3 weights; outputs are contiguous in g_Wt.
struct WtArgs { const float* W[3]; };

__global__ __launch_bounds__(256) void wtrans_kernel(
    WtArgs args, fp16* __restrict__ out_base)
{
    __shared__ float t[32][33];
    int tx = threadIdx.x, ty = threadIdx.y;
    int x0 = blockIdx.x * 32, y0 = blockIdx.y * 32;
    const float* W = args.W[blockIdx.z];
    fp16* out = out_base + (size_t)blockIdx.z * HID * HID;
    #pragma unroll
    for (int r = 0; r < 32; r += 8)
        t[ty + r][tx] = W[(long)(y0 + ty + r) * HID + x0 + tx];
    __syncthreads();
    #pragma unroll
    for (int r = 0; r < 32; r += 8)
        out[(long)(x0 + ty + r) * HID + y0 + tx] = __float2half_rn(t[tx][ty + r] * 32.0f);
}

// ---------------------------------------------------------------------------
// Shared HMMA mainloop: CTA tile 128x128, BK=64, 256 threads
// (8 warps, 4Mx2N, warp tile 32x64), 3-stage cp.async, ONE sync per chunk.
// ---------------------------------------------------------------------------
#define TILE_B   16384                 // 128 rows x 128 bytes (64 fp16)
#define STAGES   3
#define SMEM_GEMM (STAGES * 2 * TILE_B + 1024)   // 99328

// Load one 128x64 fp16 tile (global, row stride ldk elems) into swizzled SMEM.
__device__ __forceinline__ void load_tile_async(
    uint32_t dst, const fp16* __restrict__ src, int ldk, int tid)
{
    #pragma unroll
    for (int i = 0; i < 4; i++) {
        int s = tid + i * 256;
        int row = s >> 3, seg = s & 7;
        uint32_t off = row * 128 + seg * 16;
        cp_async16(dst + sw128(off), src + (long)row * ldk + seg * 8);
    }
}

// Mainloop: accumulates Ah * Bh^T over K into acc.
__device__ __forceinline__ void gemm_mainloop_p1(
    uint32_t tiles, const fp16* Ah, const fp16* Bh, int K, int tid,
    float acc[2][8][4])
{
    const int lane = tid & 31;
    const int w = tid >> 5;
    const int wm = w & 3, wn = w >> 2;
    const int nchunks = K / 64;

    auto issue_chunk = [&](int cc) {
        const uint32_t buf = tiles + (uint32_t)(cc % STAGES) * (2 * TILE_B);
        const long k0 = (long)cc * 64;
        load_tile_async(buf, Ah + k0, K, tid);
        load_tile_async(buf + TILE_B, Bh + k0, K, tid);
        cp_commit();
    };
    issue_chunk(0);
    issue_chunk(1);

    const int arow = wm * 32 + (lane & 15);
    const int brow = wn * 64 + (lane & 15);
    const uint32_t kseg = (lane >> 4) * 16;

    for (int c = 0; c < nchunks; c++) {
        if (c + 1 < nchunks) cp_wait<1>(); else cp_wait<0>();
        __syncthreads();          // all warps done with chunk c-1's buffer
        if (c + 2 < nchunks) issue_chunk(c + 2);   // overwrites buffer (c-1)%3

        const uint32_t buf = tiles + (uint32_t)(c % STAGES) * (2 * TILE_B);
        const uint32_t As = buf;
        const uint32_t Bs = buf + TILE_B;

        #pragma unroll
        for (int ks = 0; ks < 4; ks++) {
            const uint32_t kb = ks * 32 + kseg;
            uint32_t ah[2][4];
            #pragma unroll
            for (int mt = 0; mt < 2; mt++) {
                uint32_t off = (uint32_t)(arow + mt * 16) * 128 + kb;
                ldsm4(ah[mt], As + sw128(off));
            }
            #pragma unroll
            for (int nt2 = 0; nt2 < 4; nt2++) {
                uint32_t off = (uint32_t)(brow + nt2 * 16) * 128 + kb;
                uint32_t rh[4];
                ldsm4(rh, Bs + sw128(off));
                uint32_t b0h[2] = {rh[0], rh[2]}, b1h[2] = {rh[1], rh[3]};
                mma16816(acc[0][nt2 * 2 + 0], ah[0], b0h);
                mma16816(acc[0][nt2 * 2 + 1], ah[0], b1h);
                mma16816(acc[1][nt2 * 2 + 0], ah[1], b0h);
                mma16816(acc[1][nt2 * 2 + 1], ah[1], b1h);
            }
        }
    }
}

// ---------------------------------------------------------------------------
// Q/K projection: grid.z in {0,1} selects (W, bias, out).
// out[z] = fp16( (Xh @ Wt[z]^T) / 32 + bias[z] )
// ---------------------------------------------------------------------------
struct QKArgs {
    const fp16* W;         // g_Wt base
    const float* b[2];
    fp16* out[2];
};

__global__ __launch_bounds__(256) void qk_kernel(
    const fp16* __restrict__ Xh, QKArgs args)
{
    extern __shared__ char smem[];
    const uint32_t tiles = (smem_u32(smem) + 1023) & ~1023u;

    const int tid = threadIdx.x;
    const int lane = tid & 31;
    const int w = tid >> 5;
    const int wm = w & 3, wn = w >> 2;
    const int bn = blockIdx.x, bm = blockIdx.y, bz = blockIdx.z;

    const fp16* Ah = Xh + (long)(bm * 128) * HID;
    const fp16* Bh = args.W + (size_t)bz * HID * HID + (long)(bn * 128) * HID;
    const float* bias = args.b[bz];
    fp16* out = args.out[bz];

    float acc[2][8][4];
    #pragma unroll
    for (int mt = 0; mt < 2; mt++)
        #pragma unroll
        for (int nt = 0; nt < 8; nt++)
            #pragma unroll
            for (int r = 0; r < 4; r++) acc[mt][nt][r] = 0.f;

    gemm_mainloop_p1(tiles, Ah, Bh, HID, tid, acc);

    const int qr = lane >> 2, qc = lane & 3;
    #pragma unroll
    for (int mt = 0; mt < 2; mt++)
        #pragma unroll
        for (int half_ = 0; half_ < 2; half_++) {
            const long row = (long)(bm * 128 + wm * 32 + mt * 16 + qr + half_ * 8);
            const long cb = row * HID;
            #pragma unroll
            for (int nt = 0; nt < 8; nt++) {
                const int col = bn * 128 + wn * 64 + nt * 8 + qc * 2;
                float v0 = acc[mt][nt][half_ * 2 + 0] * (1.0f / 32.0f) + bias[col];
                float v1 = acc[mt][nt][half_ * 2 + 1] * (1.0f / 32.0f) + bias[col + 1];
                *(half2*)(out + cb + col) = __floats2half2_rn(v0, v1);
            }
        }
}

// ---------------------------------------------------------------------------
// V-transposed projection: Vt[z][d][s] = fp16( (Wt_v @ X[z]^T)[d][s]/32 + bv[d] )
// A = Wt_v [H,H] K-major (rows = d), B = Xh[z] [S,H] K-major (rows = s).
// grid: x = s-tile (16), y = d-tile (8), z = batch (8).
// ---------------------------------------------------------------------------
__global__ __launch_bounds__(256) void vt_kernel(
    const fp16* __restrict__ Wv, const fp16* __restrict__ Xh,
    const float* __restrict__ bv, fp16* __restrict__ Vt)
{
    extern __shared__ char smem[];
    const uint32_t tiles = (smem_u32(smem) + 1023) & ~1023u;

    const int tid = threadIdx.x;
    const int lane = tid & 31;
    const int w = tid >> 5;
    const int wm = w & 3, wn = w >> 2;
    const int bn = blockIdx.x, bm = blockIdx.y, bz = blockIdx.z;

    const fp16* Ah = Wv + (long)(bm * 128) * HID;                       // d rows
    const fp16* Bh = Xh + (long)bz * SEQ * HID + (long)(bn * 128) * HID; // s rows
    fp16* out = Vt + (long)bz * HID * SEQ;

    float acc[2][8][4];
    #pragma unroll
    for (int mt = 0; mt < 2; mt++)
        #pragma unroll
        for (int nt = 0; nt < 8; nt++)
            #pragma unroll
            for (int r = 0; r < 4; r++) acc[mt][nt][r] = 0.f;

    gemm_mainloop_p1(tiles, Ah, Bh, HID, tid, acc);

    const int qr = lane >> 2, qc = lane & 3;
    #pragma unroll
    for (int mt = 0; mt < 2; mt++)
        #pragma unroll
        for (int half_ = 0; half_ < 2; half_++) {
            const int row = bm * 128 + wm * 32 + mt * 16 + qr + half_ * 8;   // d
            const float bias = bv[row];
            const long cb = (long)row * SEQ;
            #pragma unroll
            for (int nt = 0; nt < 8; nt++) {
                const int col = bn * 128 + wn * 64 + nt * 8 + qc * 2;        // s
                float v0 = acc[mt][nt][half_ * 2 + 0] * (1.0f / 32.0f) + bias;
                float v1 = acc[mt][nt][half_ * 2 + 1] * (1.0f / 32.0f) + bias;
                *(half2*)(out + cb + col) = __floats2half2_rn(v0, v1);
            }
        }
}

// ---------------------------------------------------------------------------
// Generic 1-product GEMM, fp32 out: C = (Ah @ Bh^T) * cscale
// ---------------------------------------------------------------------------
__global__ __launch_bounds__(256) void gemm_p1_kernel(
    const fp16* __restrict__ Ah, const fp16* __restrict__ Bh, float cscale,
    float* __restrict__ Cf, int K, int Ncols, long sA, long sB, long sC)
{
    extern __shared__ char smem[];
    const uint32_t tiles = (smem_u32(smem) + 1023) & ~1023u;

    const int tid = threadIdx.x;
    const int lane = tid & 31;
    const int w = tid >> 5;
    const int wm = w & 3, wn = w >> 2;
    const int bn = blockIdx.x, bm = blockIdx.y, bz = blockIdx.z;

    Ah += bz * sA + (long)(bm * 128) * K;
    Bh += bz * sB + (long)(bn * 128) * K;

    float acc[2][8][4];
    #pragma unroll
    for (int mt = 0; mt < 2; mt++)
        #pragma unroll
        for (int nt = 0; nt < 8; nt++)
            #pragma unroll
            for (int r = 0; r < 4; r++) acc[mt][nt][r] = 0.f;

    gemm_mainloop_p1(tiles, Ah, Bh, K, tid, acc);

    const int qr = lane >> 2, qc = lane & 3;
    #pragma unroll
    for (int mt = 0; mt < 2; mt++)
        #pragma unroll
        for (int half_ = 0; half_ < 2; half_++) {
            const long row = (long)(bm * 128 + wm * 32 + mt * 16 + qr + half_ * 8);
            const long cb = bz * sC + row * Ncols;
            #pragma unroll
            for (int nt = 0; nt < 8; nt++) {
                const int col = bn * 128 + wn * 64 + nt * 8 + qc * 2;
                float v0 = acc[mt][nt][half_ * 2 + 0] * cscale;
                float v1 = acc[mt][nt][half_ * 2 + 1] * cscale;
                *(float2*)(Cf + cb + col) = make_float2(v0, v1);
            }
        }
}

// ---------------------------------------------------------------------------
// Softmax over rows of scores [B,S,S] (already scaled by 1/32 in QK epilogue).
// Single global read (row cached in smem); emits probs as single fp16.
// ---------------------------------------------------------------------------
__global__ __launch_bounds__(256) void softmax_kernel(
    const float* __restrict__ S, const int* __restrict__ mask, fp16* __restrict__ P)
{
    const int row = blockIdx.x;
    const int b   = blockIdx.y;
    const long off = ((long)b * SEQ + row) * SEQ;
    const float* ptr = S + off;
    const int* mrow = mask + (long)b * SEQ;
    const int tid = threadIdx.x;

    __shared__ float buf[SEQ];
    __shared__ float red[256];

    float m = -INFINITY;
    #pragma unroll
    for (int k = tid * 4; k < SEQ; k += 1024) {
        float4 s = *(const float4*)(ptr + k);
        int4 mk = *(const int4*)(mrow + k);
        s.x = (mk.x == 0) ? -INFINITY : s.x;
        s.y = (mk.y == 0) ? -INFINITY : s.y;
        s.z = (mk.z == 0) ? -INFINITY : s.z;
        s.w = (mk.w == 0) ? -INFINITY : s.w;
        *(float4*)(buf + k) = s;
        m = fmaxf(m, fmaxf(fmaxf(s.x, s.y), fmaxf(s.z, s.w)));
    }
    red[tid] = m; __syncthreads();
    for (int o = 128; o > 0; o >>= 1) {
        if (tid < o) red[tid] = fmaxf(red[tid], red[tid + o]);
        __syncthreads();
    }
    m = red[0];
    __syncthreads();

    float sum = 0.f;
    #pragma unroll
    for (int k = tid * 4; k < SEQ; k += 1024) {
        float4 s = *(float4*)(buf + k);
        s.x = __expf(s.x - m); s.y = __expf(s.y - m);
        s.z = __expf(s.z - m); s.w = __expf(s.w - m);
        *(float4*)(buf + k) = s;
        sum += s.x + s.y + s.z + s.w;
    }
    red[tid] = sum; __syncthreads();
    for (int o = 128; o > 0; o >>= 1) {
        if (tid < o) red[tid] += red[tid + o];
        __syncthreads();
    }
    const float inv = 1.f / red[0];

    #pragma unroll
    for (int k = tid * 4; k < SEQ; k += 1024) {
        float4 e = *(float4*)(buf + k);
        *(half2*)(P + off + k)     = __floats2half2_rn(e.x * inv, e.y * inv);
        *(half2*)(P + off + k + 2) = __floats2half2_rn(e.z * inv, e.w * inv);
    }
}

// ---------------------------------------------------------------------------
extern "C" void kernel_launch(void* const* d_in, const int* in_sizes, int n_in,
                              void* d_out, int out_size)
{
    const float* inp  = (const float*)d_in[0];
    const int*   mask = (const int*)  d_in[1];
    const float* Wq   = (const float*)d_in[2];
    const float* bq   = (const float*)d_in[3];
    const float* Wk   = (const float*)d_in[4];
    const float* bk   = (const float*)d_in[5];
    const float* Wv   = (const float*)d_in[6];
    const float* bv   = (const float*)d_in[7];
    float* out = (float*)d_out;

    fp16 *Xh, *Wt, *Qh, *Kh, *Vt, *P;
    float *Sc;
    cudaGetSymbolAddress((void**)&Xh, g_Xh);
    cudaGetSymbolAddress((void**)&Wt, g_Wt);
    cudaGetSymbolAddress((void**)&Qh, g_Qh);
    cudaGetSymbolAddress((void**)&Kh, g_Kh);
    cudaGetSymbolAddress((void**)&Vt, g_Vt);
    cudaGetSymbolAddress((void**)&P, g_P);
    cudaGetSymbolAddress((void**)&Sc, g_S);

    cudaFuncSetAttribute(qk_kernel,
                         cudaFuncAttributeMaxDynamicSharedMemorySize, SMEM_GEMM);
    cudaFuncSetAttribute(vt_kernel,
                         cudaFuncAttributeMaxDynamicSharedMemorySize, SMEM_GEMM);
    cudaFuncSetAttribute(gemm_p1_kernel,
                         cudaFuncAttributeMaxDynamicSharedMemorySize, SMEM_GEMM);

    // 1) round input to fp16
    const long nX = (long)BS * HID;
    round_kernel<<<(unsigned)(nX / 1024), 256>>>(inp, Xh, nX);

    // 2) transpose weights (x32) into contiguous fp16 buffer (one launch)
    WtArgs wa;  wa.W[0] = Wq;  wa.W[1] = Wk;  wa.W[2] = Wv;
    wtrans_kernel<<<dim3(HID / 32, HID / 32, 3), dim3(32, 8)>>>(wa, Wt);

    // 3) Q,K projections (1-product): z in {Q,K}
    QKArgs qa;
    qa.W = Wt;
    qa.b[0] = bq;  qa.b[1] = bk;
    qa.out[0] = Qh; qa.out[1] = Kh;
    dim3 gblk(256);
    qk_kernel<<<dim3(HID / 128, BS / 128, 2), gblk, SMEM_GEMM>>>(Xh, qa);

    // 4) V-transposed projection directly: Vt[z] = Wt_v @ X[z]^T
    vt_kernel<<<dim3(SEQ / 128, HID / 128, BATCH), gblk, SMEM_GEMM>>>(
        Wt + 2 * (size_t)HID * HID, Xh, bv, Vt);

    // 5) scores = (Q @ K^T)/32 (batched, 1-product), fp32 out
    gemm_p1_kernel<<<dim3(SEQ / 128, SEQ / 128, BATCH), gblk, SMEM_GEMM>>>(
        Qh, Kh, 1.0f / 32.0f, Sc,
        HID, SEQ, (long)SEQ * HID, (long)SEQ * HID, (long)SEQ * SEQ);

    // 6) masked softmax -> probs fp16
    softmax_kernel<<<dim3(SEQ, BATCH), 256>>>(Sc, mask, P);

    // 7) out = P @ Vt^T (batched, 1-product), fp32 out
    gemm_p1_kernel<<<dim3(HID / 128, SEQ / 128, BATCH), gblk, SMEM_GEMM>>>(
        P, Vt, 1.0f, out,
        SEQ, HID, (long)SEQ * SEQ, (long)SEQ * HID, (long)SEQ * HID);
}